// round 10
// baseline (speedup 1.0000x reference)
#include <cuda_runtime.h>
#include <math_constants.h>

// Causal sliding-window min, W = 128 == segment size (van Herk / Gil-Werman).
// out[seg g, p] = min(pref_g[p], suf_{g-1}[p+1]),  suf[128] := +inf.
//
// R5 structure: warp-per-segment, 4 elems/lane, SEGW=8 contiguous segments
// per warp plus a redundantly loaded halo segment (suffix only; 12.5%
// overhead). Front-batched loads (MLP=9). Register-resident suffix handoff:
// lane l needs suf_prev at 4l+1..4l+4 = {ps1,ps2,ps3,psc}.
// One 5-step shfl_xor butterfly per segment gives both directional scans.
// New vs R5: warp-uniform SAFE split (interior warps have zero bounds
// checks), e3 = min(F, psc) shortcut, final butterfly A-update elided.

#define WSZ     128
#define NWARPS  8
#define BLOCK   (NWARPS * 32)     // 256 threads
#define SEGW    8                 // segments per warp
#define SEGS    (NWARPS * SEGW)   // 64 segments per CTA
#define TILE    (SEGS * WSZ)      // 8192 elements per CTA

__device__ __forceinline__ float4 ld_guard(const float* __restrict__ x,
                                           int base, int n)
{
    const float INF = CUDART_INF_F;
    float4 v;
    v.x = (base >= 0 && base + 0 < n) ? x[base + 0] : INF;
    v.y = (base >= 0 && base + 1 < n) ? x[base + 1] : INF;
    v.z = (base >= 0 && base + 2 < n) ? x[base + 2] : INF;
    v.w = (base >= 0 && base + 3 < n) ? x[base + 3] : INF;
    return v;
}

template<bool SAFE>
__device__ __forceinline__ void run_warp(const float* __restrict__ x,
                                         float* __restrict__ out,
                                         int wbase, int n, int lane)
{
    const float INF = CUDART_INF_F;

    // ---------------- front-batched loads (MLP = 9) ----------------
    float4 vh = SAFE ? *(const float4*)(x + (wbase - WSZ))
                     : ld_guard(x, wbase - WSZ, n);
    float4 vr[SEGW];
    #pragma unroll
    for (int k = 0; k < SEGW; k++)
        vr[k] = SAFE ? *(const float4*)(x + (wbase + k * WSZ))
                     : ld_guard(x, wbase + k * WSZ, n);

    // ---------------- halo: suffix handoff registers ----------------
    float ps1, ps2, ps3, psc;
    {
        float s2 = fminf(vh.z, vh.w);
        float s1 = fminf(vh.y, s2);
        float s0 = fminf(vh.x, s1);         // lane min
        float B = s0, A = s0;               // backward-only butterfly
        #pragma unroll
        for (int d = 1; d < 32; d <<= 1) {
            float Ap = __shfl_xor_sync(0xffffffffu, A, d);
            if (!(lane & d)) B = fminf(B, Ap);
            if (d < 16)      A = fminf(A, Ap);   // last A-update dead
        }
        float sc = __shfl_down_sync(0xffffffffu, B, 1);
        if (lane == 31) sc = INF;
        ps1 = fminf(s1, sc);
        ps2 = fminf(s2, sc);
        ps3 = fminf(vh.w, sc);
        psc = sc;
    }

    // ---------------- main segments ----------------
    #pragma unroll
    for (int k = 0; k < SEGW; k++) {
        const float4 v = vr[k];

        // local prefix + suffix chains (independent, 3 deps each)
        float p1 = fminf(v.y, v.x);
        float p2 = fminf(v.z, p1);
        float s2 = fminf(v.z, v.w);
        float s1 = fminf(v.y, s2);
        float s0 = fminf(v.x, s1);          // lane min

        // bidirectional butterfly over the 32 lane-mins
        float F = s0, B = s0, A = s0;
        #pragma unroll
        for (int d = 1; d < 32; d <<= 1) {
            float Ap = __shfl_xor_sync(0xffffffffu, A, d);
            if (lane & d) F = fminf(F, Ap);
            else          B = fminf(B, Ap);
            if (d < 16)   A = fminf(A, Ap);      // last A-update dead
        }
        float pc = __shfl_up_sync(0xffffffffu, F, 1);    // excl prefix carry
        if (lane == 0) pc = INF;
        float sc = __shfl_down_sync(0xffffffffu, B, 1);  // excl suffix carry
        if (lane == 31) sc = INF;

        // combine: full prefix ∧ previous-segment suffix (register-resident)
        float e0 = fminf(fminf(v.x, pc), ps1);
        float e1 = fminf(fminf(p1,  pc), ps2);
        float e2 = fminf(fminf(p2,  pc), ps3);
        float e3 = fminf(F, psc);           // F == full inclusive prefix here

        int base = wbase + k * WSZ;
        if (SAFE) {
            __stcs((float4*)(out + base), make_float4(e0, e1, e2, e3));
        } else if (base >= 0 && base < n) {
            out[base] = e0;
            if (base + 1 < n) out[base + 1] = e1;
            if (base + 2 < n) out[base + 2] = e2;
            if (base + 3 < n) out[base + 3] = e3;
        }

        // suffix handoff to next segment
        ps1 = fminf(s1, sc);
        ps2 = fminf(s2, sc);
        ps3 = fminf(v.w, sc);
        psc = sc;
    }
}

__global__ __launch_bounds__(BLOCK)
void swmin128_kernel(const float* __restrict__ x,
                     float* __restrict__ out,
                     int n)
{
    const int lane = threadIdx.x & 31;
    const int wid  = threadIdx.x >> 5;
    const int wseg  = blockIdx.x * SEGS + wid * SEGW;
    const int wbase = wseg * WSZ + lane * 4;

    // warp-uniform safety: halo in-bounds below and all segments inside n
    const bool safe = (wseg >= 1) && ((wseg + SEGW) * WSZ <= n);
    if (safe) run_warp<true >(x, out, wbase, n, lane);
    else      run_warp<false>(x, out, wbase, n, lane);
}

extern "C" void kernel_launch(void* const* d_in, const int* in_sizes, int n_in,
                              void* d_out, int out_size)
{
    const float* x = (const float*)d_in[0];
    float* out = (float*)d_out;
    int n = in_sizes[0];
    int grid = (n + TILE - 1) / TILE;   // 1024 for N = 8,388,608
    swmin128_kernel<<<grid, BLOCK>>>(x, out, n);
}

// round 11
// speedup vs baseline: 1.2948x; 1.2948x over previous
#include <cuda_runtime.h>
#include <math_constants.h>

// Causal sliding-window min, W = 128 == segment size (van Herk / Gil-Werman).
// out[seg g, p] = min(pref_g[p], suf_{g-1}[p+1]),  suf[128] := +inf.
//
// FAST kernel (no bounds checks): each warp = two independent 16-lane
// half-runs. A half-run owns SEGV=4 contiguous segments, 8 elems/lane,
// plus a redundantly loaded halo segment (suffix only). One warp
// instruction advances BOTH halves' segments -> ~half the warp-instr per
// output vs 32-lane layout, and the butterfly is 4 steps instead of 5.
// Register-resident suffix handoff: lane needs suf_prev[8l+1..8l+8] =
// {ps1..ps7, psc}. Boundary work goes to a separate guarded TAIL kernel
// (separate kernel => separate register allocation).

#define WSZ    128
#define BLOCK  256
#define SEGV   4                     // segments per 16-lane half-run
#define RUNS   (BLOCK / 16)          // 16 half-runs per CTA
#define SEGS   (RUNS * SEGV)         // 64 segments per CTA
#define TILE   (SEGS * WSZ)          // 8192 elements per CTA

__global__ __launch_bounds__(BLOCK)
void swmin_fast(const float* __restrict__ x,
                float* __restrict__ out)
{
    const float INF = CUDART_INF_F;
    const int tid  = threadIdx.x;
    const int lane = tid & 31;
    const int ll   = lane & 15;                       // lane within half-run

    const int rseg0 = blockIdx.x * SEGS + (tid >> 4) * SEGV;
    const int lbase = rseg0 * WSZ + ll * 8;           // this lane's first elem

    // ---------------- front-batched loads (MLP = 10) ----------------
    float4 h0, h1;
    {
        int hb = lbase - WSZ;
        if (hb >= 0) {
            h0 = *(const float4*)(x + hb);
            h1 = *(const float4*)(x + hb + 4);
        } else {
            h0 = make_float4(INF, INF, INF, INF);
            h1 = h0;
        }
    }
    float4 va[SEGV], vb[SEGV];
    #pragma unroll
    for (int k = 0; k < SEGV; k++) {
        int base = lbase + k * WSZ;
        va[k] = *(const float4*)(x + base);
        vb[k] = *(const float4*)(x + base + 4);
    }

    // ---------------- halo: suffix handoff registers ----------------
    float ps1, ps2, ps3, ps4, ps5, ps6, ps7, psc;
    {
        float s6 = fminf(h1.z, h1.w);
        float s5 = fminf(h1.y, s6);
        float s4 = fminf(h1.x, s5);
        float s3 = fminf(h0.w, s4);
        float s2 = fminf(h0.z, s3);
        float s1 = fminf(h0.y, s2);
        float s0 = fminf(h0.x, s1);       // lane min
        float B = s0, A = s0;             // backward-only 4-step butterfly
        #pragma unroll
        for (int d = 1; d < 16; d <<= 1) {
            float Ap = __shfl_xor_sync(0xffffffffu, A, d);
            if (!(lane & d)) B = fminf(B, Ap);
            if (d < 8)       A = fminf(A, Ap);
        }
        float sc = __shfl_down_sync(0xffffffffu, B, 1);
        if (ll == 15) sc = INF;
        ps1 = fminf(s1, sc); ps2 = fminf(s2, sc);
        ps3 = fminf(s3, sc); ps4 = fminf(s4, sc);
        ps5 = fminf(s5, sc); ps6 = fminf(s6, sc);
        ps7 = fminf(h1.w, sc); psc = sc;
    }

    // ---------------- main segments ----------------
    #pragma unroll
    for (int k = 0; k < SEGV; k++) {
        const float4 v0 = va[k];
        const float4 v1 = vb[k];

        // local prefix chain (7) and suffix chain (7), independent
        float p1 = fminf(v0.y, v0.x);
        float p2 = fminf(v0.z, p1);
        float p3 = fminf(v0.w, p2);
        float p4 = fminf(v1.x, p3);
        float p5 = fminf(v1.y, p4);
        float p6 = fminf(v1.z, p5);
        float s6 = fminf(v1.z, v1.w);
        float s5 = fminf(v1.y, s6);
        float s4 = fminf(v1.x, s5);
        float s3 = fminf(v0.w, s4);
        float s2 = fminf(v0.z, s3);
        float s1 = fminf(v0.y, s2);
        float s0 = fminf(v0.x, s1);       // lane min

        // bidirectional 4-step butterfly over the 16 lane-mins
        float F = s0, B = s0, A = s0;
        #pragma unroll
        for (int d = 1; d < 16; d <<= 1) {
            float Ap = __shfl_xor_sync(0xffffffffu, A, d);
            if (lane & d) F = fminf(F, Ap);
            else          B = fminf(B, Ap);
            if (d < 8)    A = fminf(A, Ap);
        }
        float pc = __shfl_up_sync(0xffffffffu, F, 1);    // excl prefix carry
        if (ll == 0) pc = INF;
        float sc = __shfl_down_sync(0xffffffffu, B, 1);  // excl suffix carry
        if (ll == 15) sc = INF;

        // combine: full prefix ∧ previous-segment suffix
        float e0 = fminf(fminf(v0.x, pc), ps1);
        float e1 = fminf(fminf(p1, pc), ps2);
        float e2 = fminf(fminf(p2, pc), ps3);
        float e3 = fminf(fminf(p3, pc), ps4);
        float e4 = fminf(fminf(p4, pc), ps5);
        float e5 = fminf(fminf(p5, pc), ps6);
        float e6 = fminf(fminf(p6, pc), ps7);
        float e7 = fminf(F, psc);         // F == full inclusive prefix here

        int base = lbase + k * WSZ;
        __stcs((float4*)(out + base),     make_float4(e0, e1, e2, e3));
        __stcs((float4*)(out + base + 4), make_float4(e4, e5, e6, e7));

        // suffix handoff to next segment
        ps1 = fminf(s1, sc); ps2 = fminf(s2, sc);
        ps3 = fminf(s3, sc); ps4 = fminf(s4, sc);
        ps5 = fminf(s5, sc); ps6 = fminf(s6, sc);
        ps7 = fminf(v1.w, sc); psc = sc;
    }
}

// ---------------- generic guarded tail: one segment per warp ----------------
__global__ __launch_bounds__(BLOCK)
void swmin_tail(const float* __restrict__ x,
                float* __restrict__ out,
                int n, int seg_lo)
{
    const float INF = CUDART_INF_F;
    const int lane = threadIdx.x & 31;
    const int seg  = seg_lo + blockIdx.x * (BLOCK / 32) + (threadIdx.x >> 5);
    const int base = seg * WSZ + lane * 4;
    if (seg * WSZ >= n) return;

    // halo (previous segment), guarded
    float4 vh;
    {
        int hb = base - WSZ;
        vh.x = (hb >= 0 && hb + 0 < n) ? x[hb + 0] : INF;
        vh.y = (hb >= 0 && hb + 1 < n) ? x[hb + 1] : INF;
        vh.z = (hb >= 0 && hb + 2 < n) ? x[hb + 2] : INF;
        vh.w = (hb >= 0 && hb + 3 < n) ? x[hb + 3] : INF;
    }
    float4 v;
    v.x = (base + 0 < n) ? x[base + 0] : INF;
    v.y = (base + 1 < n) ? x[base + 1] : INF;
    v.z = (base + 2 < n) ? x[base + 2] : INF;
    v.w = (base + 3 < n) ? x[base + 3] : INF;

    // halo suffix values at 4l+1..4l+4
    float ps1, ps2, ps3, psc;
    {
        float s2 = fminf(vh.z, vh.w);
        float s1 = fminf(vh.y, s2);
        float s0 = fminf(vh.x, s1);
        float B = s0, A = s0;
        #pragma unroll
        for (int d = 1; d < 32; d <<= 1) {
            float Ap = __shfl_xor_sync(0xffffffffu, A, d);
            if (!(lane & d)) B = fminf(B, Ap);
            A = fminf(A, Ap);
        }
        float sc = __shfl_down_sync(0xffffffffu, B, 1);
        if (lane == 31) sc = INF;
        ps1 = fminf(s1, sc); ps2 = fminf(s2, sc);
        ps3 = fminf(vh.w, sc); psc = sc;
    }

    float p1 = fminf(v.y, v.x);
    float p2 = fminf(v.z, p1);
    float p3 = fminf(v.w, p2);
    float s2 = fminf(v.z, v.w);
    float s1 = fminf(v.y, s2);
    float s0 = fminf(v.x, s1);

    float F = s0, B = s0, A = s0;
    #pragma unroll
    for (int d = 1; d < 32; d <<= 1) {
        float Ap = __shfl_xor_sync(0xffffffffu, A, d);
        if (lane & d) F = fminf(F, Ap);
        else          B = fminf(B, Ap);
        A = fminf(A, Ap);
    }
    float pc = __shfl_up_sync(0xffffffffu, F, 1);
    if (lane == 0) pc = INF;

    float e0 = fminf(fminf(v.x, pc), ps1);
    float e1 = fminf(fminf(p1, pc), ps2);
    float e2 = fminf(fminf(p2, pc), ps3);
    float e3 = fminf(fminf(p3, pc), psc);

    if (base + 0 < n) out[base + 0] = e0;
    if (base + 1 < n) out[base + 1] = e1;
    if (base + 2 < n) out[base + 2] = e2;
    if (base + 3 < n) out[base + 3] = e3;
}

extern "C" void kernel_launch(void* const* d_in, const int* in_sizes, int n_in,
                              void* d_out, int out_size)
{
    const float* x = (const float*)d_in[0];
    float* out = (float*)d_out;
    int n = in_sizes[0];

    int full_tiles = n / TILE;                 // 1024 for N = 8,388,608
    if (full_tiles > 0)
        swmin_fast<<<full_tiles, BLOCK>>>(x, out);

    int seg_lo = full_tiles * SEGS;
    int n_segs = (n + WSZ - 1) / WSZ;
    int tail_segs = n_segs - seg_lo;           // 0 for N = 8,388,608
    if (tail_segs > 0) {
        int warps_per_blk = BLOCK / 32;
        int blocks = (tail_segs + warps_per_blk - 1) / warps_per_blk;
        swmin_tail<<<blocks, BLOCK>>>(x, out, n, seg_lo);
    }
}

// round 12
// speedup vs baseline: 1.3175x; 1.0175x over previous
#include <cuda_runtime.h>
#include <math_constants.h>

// Causal sliding-window min, W = 128 == segment size (van Herk / Gil-Werman).
// out[seg g, p] = min(pref_g[p], suf_{g-1}[p+1]),  suf[128] := +inf.
//
// FAST kernel (no bounds checks): each warp = two independent 16-lane
// half-runs; a half-run owns SEGV=4 contiguous segments, 8 elems/lane, plus
// a redundantly loaded halo segment (suffix only). Segments are processed in
// PAIRS with their 4-step shfl_xor butterflies interleaved, so two
// independent SHFL chains are in flight (hides MIO latency). Register-
// resident suffix handoff: lane needs suf_prev[8l+1..8l+8] = {ps1..ps7,psc}.
// Boundary work in a separate guarded tail kernel (separate reg allocation).

#define WSZ    128
#define BLOCK  256
#define SEGV   4                     // segments per 16-lane half-run
#define RUNS   (BLOCK / 16)          // 16 half-runs per CTA
#define SEGS   (RUNS * SEGV)         // 64 segments per CTA
#define TILE   (SEGS * WSZ)          // 8192 elements per CTA

__global__ __launch_bounds__(BLOCK)
void swmin_fast(const float* __restrict__ x,
                float* __restrict__ out)
{
    const float INF = CUDART_INF_F;
    const int tid  = threadIdx.x;
    const int lane = tid & 31;
    const int ll   = lane & 15;                       // lane within half-run

    const int rseg0 = blockIdx.x * SEGS + (tid >> 4) * SEGV;
    const int lbase = rseg0 * WSZ + ll * 8;           // this lane's first elem

    // ---------------- front-batched loads (MLP = 10) ----------------
    float4 h0, h1;
    {
        int hb = lbase - WSZ;
        if (hb >= 0) {
            h0 = *(const float4*)(x + hb);
            h1 = *(const float4*)(x + hb + 4);
        } else {
            h0 = make_float4(INF, INF, INF, INF);
            h1 = h0;
        }
    }
    float4 va[SEGV], vb[SEGV];
    #pragma unroll
    for (int k = 0; k < SEGV; k++) {
        int base = lbase + k * WSZ;
        va[k] = *(const float4*)(x + base);
        vb[k] = *(const float4*)(x + base + 4);
    }

    // ---------------- halo: suffix handoff registers ----------------
    float ps1, ps2, ps3, ps4, ps5, ps6, ps7, psc;
    {
        float s6 = fminf(h1.z, h1.w);
        float s5 = fminf(h1.y, s6);
        float s4 = fminf(h1.x, s5);
        float s3 = fminf(h0.w, s4);
        float s2 = fminf(h0.z, s3);
        float s1 = fminf(h0.y, s2);
        float s0 = fminf(h0.x, s1);       // lane min
        float B = s0, A = s0;             // backward-only 4-step butterfly
        #pragma unroll
        for (int d = 1; d < 16; d <<= 1) {
            float Ap = __shfl_xor_sync(0xffffffffu, A, d);
            if (!(lane & d)) B = fminf(B, Ap);
            if (d < 8)       A = fminf(A, Ap);
        }
        float sc = __shfl_down_sync(0xffffffffu, B, 1);
        if (ll == 15) sc = INF;
        ps1 = fminf(s1, sc); ps2 = fminf(s2, sc);
        ps3 = fminf(s3, sc); ps4 = fminf(s4, sc);
        ps5 = fminf(s5, sc); ps6 = fminf(s6, sc);
        ps7 = fminf(h1.w, sc); psc = sc;
    }

    // ---------------- segment pairs, butterflies interleaved ----------------
    #pragma unroll
    for (int pr = 0; pr < SEGV / 2; pr++) {
        const float4 a0 = va[2 * pr + 0], a1 = vb[2 * pr + 0];
        const float4 b0 = va[2 * pr + 1], b1 = vb[2 * pr + 1];

        // local prefix chains (7-deep) and suffix chains, a and b independent
        float pa1 = fminf(a0.y, a0.x);
        float pa2 = fminf(a0.z, pa1);
        float pa3 = fminf(a0.w, pa2);
        float pa4 = fminf(a1.x, pa3);
        float pa5 = fminf(a1.y, pa4);
        float pa6 = fminf(a1.z, pa5);
        float sa6 = fminf(a1.z, a1.w);
        float sa5 = fminf(a1.y, sa6);
        float sa4 = fminf(a1.x, sa5);
        float sa3 = fminf(a0.w, sa4);
        float sa2 = fminf(a0.z, sa3);
        float sa1 = fminf(a0.y, sa2);
        float sa0 = fminf(a0.x, sa1);     // lane min of a

        float pb1 = fminf(b0.y, b0.x);
        float pb2 = fminf(b0.z, pb1);
        float pb3 = fminf(b0.w, pb2);
        float pb4 = fminf(b1.x, pb3);
        float pb5 = fminf(b1.y, pb4);
        float pb6 = fminf(b1.z, pb5);
        float sb6 = fminf(b1.z, b1.w);
        float sb5 = fminf(b1.y, sb6);
        float sb4 = fminf(b1.x, sb5);
        float sb3 = fminf(b0.w, sb4);
        float sb2 = fminf(b0.z, sb3);
        float sb1 = fminf(b0.y, sb2);
        float sb0 = fminf(b0.x, sb1);     // lane min of b

        // two interleaved 4-step bidirectional butterflies
        float Fa = sa0, Ba = sa0, Aa = sa0;
        float Fb = sb0, Bb = sb0, Ab = sb0;
        #pragma unroll
        for (int d = 1; d < 16; d <<= 1) {
            float Aap = __shfl_xor_sync(0xffffffffu, Aa, d);
            float Abp = __shfl_xor_sync(0xffffffffu, Ab, d);
            if (lane & d) { Fa = fminf(Fa, Aap); Fb = fminf(Fb, Abp); }
            else          { Ba = fminf(Ba, Aap); Bb = fminf(Bb, Abp); }
            if (d < 8)    { Aa = fminf(Aa, Aap); Ab = fminf(Ab, Abp); }
        }
        float pca = __shfl_up_sync(0xffffffffu, Fa, 1);
        float pcb = __shfl_up_sync(0xffffffffu, Fb, 1);
        float sca = __shfl_down_sync(0xffffffffu, Ba, 1);
        float scb = __shfl_down_sync(0xffffffffu, Bb, 1);
        if (ll == 0)  { pca = INF; pcb = INF; }
        if (ll == 15) { sca = INF; scb = INF; }

        // ---- combine segment a with handoff from previous segment ----
        {
            float e0 = fminf(fminf(a0.x, pca), ps1);
            float e1 = fminf(fminf(pa1, pca), ps2);
            float e2 = fminf(fminf(pa2, pca), ps3);
            float e3 = fminf(fminf(pa3, pca), ps4);
            float e4 = fminf(fminf(pa4, pca), ps5);
            float e5 = fminf(fminf(pa5, pca), ps6);
            float e6 = fminf(fminf(pa6, pca), ps7);
            float e7 = fminf(Fa, psc);    // Fa == full inclusive prefix
            int base = lbase + (2 * pr + 0) * WSZ;
            __stcs((float4*)(out + base),     make_float4(e0, e1, e2, e3));
            __stcs((float4*)(out + base + 4), make_float4(e4, e5, e6, e7));
        }

        // ---- handoff a -> b, combine segment b ----
        {
            float qa1 = fminf(sa1, sca);
            float qa2 = fminf(sa2, sca);
            float qa3 = fminf(sa3, sca);
            float qa4 = fminf(sa4, sca);
            float qa5 = fminf(sa5, sca);
            float qa6 = fminf(sa6, sca);
            float qa7 = fminf(a1.w, sca);
            float e0 = fminf(fminf(b0.x, pcb), qa1);
            float e1 = fminf(fminf(pb1, pcb), qa2);
            float e2 = fminf(fminf(pb2, pcb), qa3);
            float e3 = fminf(fminf(pb3, pcb), qa4);
            float e4 = fminf(fminf(pb4, pcb), qa5);
            float e5 = fminf(fminf(pb5, pcb), qa6);
            float e6 = fminf(fminf(pb6, pcb), qa7);
            float e7 = fminf(Fb, sca);    // Fb == full inclusive prefix
            int base = lbase + (2 * pr + 1) * WSZ;
            __stcs((float4*)(out + base),     make_float4(e0, e1, e2, e3));
            __stcs((float4*)(out + base + 4), make_float4(e4, e5, e6, e7));
        }

        // ---- handoff b -> next pair ----
        ps1 = fminf(sb1, scb); ps2 = fminf(sb2, scb);
        ps3 = fminf(sb3, scb); ps4 = fminf(sb4, scb);
        ps5 = fminf(sb5, scb); ps6 = fminf(sb6, scb);
        ps7 = fminf(b1.w, scb); psc = scb;
    }
}

// ---------------- generic guarded tail: one segment per warp ----------------
__global__ __launch_bounds__(BLOCK)
void swmin_tail(const float* __restrict__ x,
                float* __restrict__ out,
                int n, int seg_lo)
{
    const float INF = CUDART_INF_F;
    const int lane = threadIdx.x & 31;
    const int seg  = seg_lo + blockIdx.x * (BLOCK / 32) + (threadIdx.x >> 5);
    const int base = seg * WSZ + lane * 4;
    if (seg * WSZ >= n) return;

    float4 vh;
    {
        int hb = base - WSZ;
        vh.x = (hb >= 0 && hb + 0 < n) ? x[hb + 0] : INF;
        vh.y = (hb >= 0 && hb + 1 < n) ? x[hb + 1] : INF;
        vh.z = (hb >= 0 && hb + 2 < n) ? x[hb + 2] : INF;
        vh.w = (hb >= 0 && hb + 3 < n) ? x[hb + 3] : INF;
    }
    float4 v;
    v.x = (base + 0 < n) ? x[base + 0] : INF;
    v.y = (base + 1 < n) ? x[base + 1] : INF;
    v.z = (base + 2 < n) ? x[base + 2] : INF;
    v.w = (base + 3 < n) ? x[base + 3] : INF;

    float ps1, ps2, ps3, psc;
    {
        float s2 = fminf(vh.z, vh.w);
        float s1 = fminf(vh.y, s2);
        float s0 = fminf(vh.x, s1);
        float B = s0, A = s0;
        #pragma unroll
        for (int d = 1; d < 32; d <<= 1) {
            float Ap = __shfl_xor_sync(0xffffffffu, A, d);
            if (!(lane & d)) B = fminf(B, Ap);
            A = fminf(A, Ap);
        }
        float sc = __shfl_down_sync(0xffffffffu, B, 1);
        if (lane == 31) sc = INF;
        ps1 = fminf(s1, sc); ps2 = fminf(s2, sc);
        ps3 = fminf(vh.w, sc); psc = sc;
    }

    float p1 = fminf(v.y, v.x);
    float p2 = fminf(v.z, p1);
    float p3 = fminf(v.w, p2);
    float s2 = fminf(v.z, v.w);
    float s1 = fminf(v.y, s2);
    float s0 = fminf(v.x, s1);

    float F = s0, B = s0, A = s0;
    #pragma unroll
    for (int d = 1; d < 32; d <<= 1) {
        float Ap = __shfl_xor_sync(0xffffffffu, A, d);
        if (lane & d) F = fminf(F, Ap);
        else          B = fminf(B, Ap);
        A = fminf(A, Ap);
    }
    float pc = __shfl_up_sync(0xffffffffu, F, 1);
    if (lane == 0) pc = INF;

    float e0 = fminf(fminf(v.x, pc), ps1);
    float e1 = fminf(fminf(p1, pc), ps2);
    float e2 = fminf(fminf(p2, pc), ps3);
    float e3 = fminf(fminf(p3, pc), psc);

    if (base + 0 < n) out[base + 0] = e0;
    if (base + 1 < n) out[base + 1] = e1;
    if (base + 2 < n) out[base + 2] = e2;
    if (base + 3 < n) out[base + 3] = e3;
}

extern "C" void kernel_launch(void* const* d_in, const int* in_sizes, int n_in,
                              void* d_out, int out_size)
{
    const float* x = (const float*)d_in[0];
    float* out = (float*)d_out;
    int n = in_sizes[0];

    int full_tiles = n / TILE;                 // 1024 for N = 8,388,608
    if (full_tiles > 0)
        swmin_fast<<<full_tiles, BLOCK>>>(x, out);

    int seg_lo = full_tiles * SEGS;
    int n_segs = (n + WSZ - 1) / WSZ;
    int tail_segs = n_segs - seg_lo;           // 0 for N = 8,388,608
    if (tail_segs > 0) {
        int warps_per_blk = BLOCK / 32;
        int blocks = (tail_segs + warps_per_blk - 1) / warps_per_blk;
        swmin_tail<<<blocks, BLOCK>>>(x, out, n, seg_lo);
    }
}

// round 16
// speedup vs baseline: 1.5409x; 1.1696x over previous
#include <cuda_runtime.h>
#include <math_constants.h>

// Causal sliding-window min, W = 128 == segment size (van Herk / Gil-Werman).
// out[seg g, p] = min(pref_g[p], suf_{g-1}[p+1]),  suf[128] := +inf.
//
// FAST kernel = R5 structure exactly: warp-per-segment, 4 elems/lane,
// SEGW=8 contiguous segments per warp + redundantly loaded halo segment
// (suffix only; 12.5% overhead). Front-batched loads (MLP=9). Register-
// resident suffix handoff {ps1,ps2,ps3,psc}. One 5-step shfl_xor butterfly
// per segment gives both directional scans.
// All bounds handling lives in a separate guarded tail kernel (separate
// kernel => separate register allocation). Fast kernel's only predicate is
// the warp-uniform halo hb >= 0.

#define WSZ     128
#define NWARPS  8
#define BLOCK   (NWARPS * 32)     // 256 threads
#define SEGW    8                 // segments per warp
#define SEGS    (NWARPS * SEGW)   // 64 segments per CTA
#define TILE    (SEGS * WSZ)      // 8192 elements per CTA

__global__ __launch_bounds__(BLOCK)
void swmin_fast(const float* __restrict__ x,
                float* __restrict__ out)
{
    const float INF = CUDART_INF_F;
    const int lane = threadIdx.x & 31;
    const int wid  = threadIdx.x >> 5;
    const int wbase = (blockIdx.x * SEGS + wid * SEGW) * WSZ + lane * 4;

    // ---------------- front-batched loads (MLP = 9) ----------------
    float4 vh;
    {
        int hb = wbase - WSZ;
        if (hb >= 0) {                      // false only for warp 0 of CTA 0
            vh = *(const float4*)(x + hb);
        } else {
            vh = make_float4(INF, INF, INF, INF);
        }
    }
    float4 vr[SEGW];
    #pragma unroll
    for (int k = 0; k < SEGW; k++)
        vr[k] = *(const float4*)(x + (wbase + k * WSZ));

    // ---------------- halo: suffix handoff registers ----------------
    float ps1, ps2, ps3, psc;
    {
        float s2 = fminf(vh.z, vh.w);
        float s1 = fminf(vh.y, s2);
        float s0 = fminf(vh.x, s1);         // lane min
        float B = s0, A = s0;               // backward-only butterfly
        #pragma unroll
        for (int d = 1; d < 32; d <<= 1) {
            float Ap = __shfl_xor_sync(0xffffffffu, A, d);
            if (!(lane & d)) B = fminf(B, Ap);
            if (d < 16)      A = fminf(A, Ap);   // final A-update dead
        }
        float sc = __shfl_down_sync(0xffffffffu, B, 1);
        if (lane == 31) sc = INF;
        ps1 = fminf(s1, sc);
        ps2 = fminf(s2, sc);
        ps3 = fminf(vh.w, sc);
        psc = sc;
    }

    // ---------------- main segments ----------------
    #pragma unroll
    for (int k = 0; k < SEGW; k++) {
        const float4 v = vr[k];

        // local prefix + suffix chains (independent, 3 deps each)
        float p1 = fminf(v.y, v.x);
        float p2 = fminf(v.z, p1);
        float s2 = fminf(v.z, v.w);
        float s1 = fminf(v.y, s2);
        float s0 = fminf(v.x, s1);          // lane min

        // bidirectional butterfly over the 32 lane-mins
        float F = s0, B = s0, A = s0;
        #pragma unroll
        for (int d = 1; d < 32; d <<= 1) {
            float Ap = __shfl_xor_sync(0xffffffffu, A, d);
            if (lane & d) F = fminf(F, Ap);
            else          B = fminf(B, Ap);
            if (d < 16)   A = fminf(A, Ap);      // final A-update dead
        }
        float pc = __shfl_up_sync(0xffffffffu, F, 1);    // excl prefix carry
        if (lane == 0) pc = INF;
        float sc = __shfl_down_sync(0xffffffffu, B, 1);  // excl suffix carry
        if (lane == 31) sc = INF;

        // combine: full prefix ∧ previous-segment suffix (registers)
        float e0 = fminf(fminf(v.x, pc), ps1);
        float e1 = fminf(fminf(p1,  pc), ps2);
        float e2 = fminf(fminf(p2,  pc), ps3);
        float e3 = fminf(F, psc);           // F == full inclusive prefix here

        __stcs((float4*)(out + (wbase + k * WSZ)),
               make_float4(e0, e1, e2, e3));

        // suffix handoff to next segment
        ps1 = fminf(s1, sc);
        ps2 = fminf(s2, sc);
        ps3 = fminf(v.w, sc);
        psc = sc;
    }
}

// ---------------- guarded tail: one segment per warp ----------------
__global__ __launch_bounds__(BLOCK)
void swmin_tail(const float* __restrict__ x,
                float* __restrict__ out,
                int n, int seg_lo)
{
    const float INF = CUDART_INF_F;
    const int lane = threadIdx.x & 31;
    const int seg  = seg_lo + blockIdx.x * (BLOCK / 32) + (threadIdx.x >> 5);
    const int base = seg * WSZ + lane * 4;
    if (seg * WSZ >= n) return;

    float4 vh;
    {
        int hb = base - WSZ;
        vh.x = (hb >= 0 && hb + 0 < n) ? x[hb + 0] : INF;
        vh.y = (hb >= 0 && hb + 1 < n) ? x[hb + 1] : INF;
        vh.z = (hb >= 0 && hb + 2 < n) ? x[hb + 2] : INF;
        vh.w = (hb >= 0 && hb + 3 < n) ? x[hb + 3] : INF;
    }
    float4 v;
    v.x = (base + 0 < n) ? x[base + 0] : INF;
    v.y = (base + 1 < n) ? x[base + 1] : INF;
    v.z = (base + 2 < n) ? x[base + 2] : INF;
    v.w = (base + 3 < n) ? x[base + 3] : INF;

    float ps1, ps2, ps3, psc;
    {
        float s2 = fminf(vh.z, vh.w);
        float s1 = fminf(vh.y, s2);
        float s0 = fminf(vh.x, s1);
        float B = s0, A = s0;
        #pragma unroll
        for (int d = 1; d < 32; d <<= 1) {
            float Ap = __shfl_xor_sync(0xffffffffu, A, d);
            if (!(lane & d)) B = fminf(B, Ap);
            A = fminf(A, Ap);
        }
        float sc = __shfl_down_sync(0xffffffffu, B, 1);
        if (lane == 31) sc = INF;
        ps1 = fminf(s1, sc); ps2 = fminf(s2, sc);
        ps3 = fminf(vh.w, sc); psc = sc;
    }

    float p1 = fminf(v.y, v.x);
    float p2 = fminf(v.z, p1);
    float p3 = fminf(v.w, p2);
    float s2 = fminf(v.z, v.w);
    float s1 = fminf(v.y, s2);
    float s0 = fminf(v.x, s1);

    float F = s0, B = s0, A = s0;
    #pragma unroll
    for (int d = 1; d < 32; d <<= 1) {
        float Ap = __shfl_xor_sync(0xffffffffu, A, d);
        if (lane & d) F = fminf(F, Ap);
        else          B = fminf(B, Ap);
        A = fminf(A, Ap);
    }
    float pc = __shfl_up_sync(0xffffffffu, F, 1);
    if (lane == 0) pc = INF;

    float e0 = fminf(fminf(v.x, pc), ps1);
    float e1 = fminf(fminf(p1, pc), ps2);
    float e2 = fminf(fminf(p2, pc), ps3);
    float e3 = fminf(fminf(p3, pc), psc);

    if (base + 0 < n) out[base + 0] = e0;
    if (base + 1 < n) out[base + 1] = e1;
    if (base + 2 < n) out[base + 2] = e2;
    if (base + 3 < n) out[base + 3] = e3;
}

extern "C" void kernel_launch(void* const* d_in, const int* in_sizes, int n_in,
                              void* d_out, int out_size)
{
    const float* x = (const float*)d_in[0];
    float* out = (float*)d_out;
    int n = in_sizes[0];

    int full_tiles = n / TILE;                 // 1024 for N = 8,388,608
    if (full_tiles > 0)
        swmin_fast<<<full_tiles, BLOCK>>>(x, out);

    int seg_lo = full_tiles * SEGS;
    int n_segs = (n + WSZ - 1) / WSZ;
    int tail_segs = n_segs - seg_lo;           // 0 for N = 8,388,608
    if (tail_segs > 0) {
        int warps_per_blk = BLOCK / 32;
        int blocks = (tail_segs + warps_per_blk - 1) / warps_per_blk;
        swmin_tail<<<blocks, BLOCK>>>(x, out, n, seg_lo);
    }
}

// round 17
// speedup vs baseline: 1.5731x; 1.0209x over previous
#include <cuda_runtime.h>
#include <math_constants.h>

// Causal sliding-window min, W = 128 == segment size (van Herk / Gil-Werman).
// out[seg g, p] = min(pref_g[p], suf_{g-1}[p+1]),  suf[128] := +inf.
//
// Single balanced wave: GRID = 592 = 4 CTAs/SM on 148 SMs. The 4736 warps
// partition all segment-PAIRS into contiguous runs of q or q+1 pairs
// (imbalance <= 1 pair). Loop-carried register suffix handoff => ONE halo
// load per warp for its whole run. Pair loads are double-buffered (next
// pair's loads issue before current pair's compute). Plain stores keep the
// output L2-resident across graph replays. Leftover segments (n not a
// multiple of 256) go to a separate guarded tail kernel.

#define WSZ    128
#define BLOCK  256
#define GRID   592                      // 4 x 148 SMs
#define NW     (BLOCK / 32)             // 8 warps per CTA
#define TW     (GRID * NW)              // 4736 warps total

// per-segment body: scan + combine + store, updates suffix handoff regs
__device__ __forceinline__ void seg_proc(const float4 v, float* __restrict__ op,
                                         int lane,
                                         float& ps1, float& ps2,
                                         float& ps3, float& psc)
{
    const float INF = CUDART_INF_F;
    float p1 = fminf(v.y, v.x);
    float p2 = fminf(v.z, p1);
    float s2 = fminf(v.z, v.w);
    float s1 = fminf(v.y, s2);
    float s0 = fminf(v.x, s1);              // lane min

    float F = s0, B = s0, A = s0;           // bidirectional butterfly
    #pragma unroll
    for (int d = 1; d < 32; d <<= 1) {
        float Ap = __shfl_xor_sync(0xffffffffu, A, d);
        if (lane & d) F = fminf(F, Ap);
        else          B = fminf(B, Ap);
        if (d < 16)   A = fminf(A, Ap);     // final A-update dead
    }
    float pc = __shfl_up_sync(0xffffffffu, F, 1);
    if (lane == 0) pc = INF;
    float sc = __shfl_down_sync(0xffffffffu, B, 1);
    if (lane == 31) sc = INF;

    float e0 = fminf(fminf(v.x, pc), ps1);
    float e1 = fminf(fminf(p1,  pc), ps2);
    float e2 = fminf(fminf(p2,  pc), ps3);
    float e3 = fminf(F, psc);               // F == full inclusive prefix

    *(float4*)op = make_float4(e0, e1, e2, e3);

    ps1 = fminf(s1, sc);
    ps2 = fminf(s2, sc);
    ps3 = fminf(v.w, sc);
    psc = sc;
}

__global__ __launch_bounds__(BLOCK)
void swmin_main(const float* __restrict__ x,
                float* __restrict__ out,
                int q, int r)           // pairs per warp: q + (gw < r)
{
    const float INF = CUDART_INF_F;
    const int lane = threadIdx.x & 31;
    const int gw   = blockIdx.x * NW + (threadIdx.x >> 5);

    const int len = q + (gw < r ? 1 : 0);         // pairs in this warp's run
    if (len == 0) return;
    const int p0  = gw * q + (gw < r ? gw : r);   // first pair index
    const int s0  = 2 * p0;                       // first segment index
    const int base = s0 * WSZ + lane * 4;

    // ---------------- halo: one load per warp-run ----------------
    float ps1, ps2, ps3, psc;
    {
        float4 vh;
        if (s0 > 0) {                              // warp-uniform
            vh = *(const float4*)(x + (base - WSZ));
        } else {
            vh = make_float4(INF, INF, INF, INF);
        }
        float s2 = fminf(vh.z, vh.w);
        float s1 = fminf(vh.y, s2);
        float sl = fminf(vh.x, s1);
        float B = sl, A = sl;
        #pragma unroll
        for (int d = 1; d < 32; d <<= 1) {
            float Ap = __shfl_xor_sync(0xffffffffu, A, d);
            if (!(lane & d)) B = fminf(B, Ap);
            if (d < 16)      A = fminf(A, Ap);
        }
        float sc = __shfl_down_sync(0xffffffffu, B, 1);
        if (lane == 31) sc = INF;
        ps1 = fminf(s1, sc);
        ps2 = fminf(s2, sc);
        ps3 = fminf(vh.w, sc);
        psc = sc;
    }

    // ---------------- pair loop, double-buffered loads ----------------
    float4 c0 = *(const float4*)(x + base);
    float4 c1 = *(const float4*)(x + base + WSZ);

    int i = 0;
    for (; i + 1 < len; i++) {
        const float* pb = x + base + (2 * i + 2) * WSZ;
        float4 n0 = *(const float4*)pb;
        float4 n1 = *(const float4*)(pb + WSZ);

        seg_proc(c0, out + base + (2 * i + 0) * WSZ, lane, ps1, ps2, ps3, psc);
        seg_proc(c1, out + base + (2 * i + 1) * WSZ, lane, ps1, ps2, ps3, psc);

        c0 = n0; c1 = n1;
    }
    seg_proc(c0, out + base + (2 * i + 0) * WSZ, lane, ps1, ps2, ps3, psc);
    seg_proc(c1, out + base + (2 * i + 1) * WSZ, lane, ps1, ps2, ps3, psc);
}

// ---------------- guarded tail: one segment per warp ----------------
__global__ __launch_bounds__(BLOCK)
void swmin_tail(const float* __restrict__ x,
                float* __restrict__ out,
                int n, int seg_lo)
{
    const float INF = CUDART_INF_F;
    const int lane = threadIdx.x & 31;
    const int seg  = seg_lo + blockIdx.x * (BLOCK / 32) + (threadIdx.x >> 5);
    const int base = seg * WSZ + lane * 4;
    if (seg * WSZ >= n) return;

    float4 vh;
    {
        int hb = base - WSZ;
        vh.x = (hb >= 0 && hb + 0 < n) ? x[hb + 0] : INF;
        vh.y = (hb >= 0 && hb + 1 < n) ? x[hb + 1] : INF;
        vh.z = (hb >= 0 && hb + 2 < n) ? x[hb + 2] : INF;
        vh.w = (hb >= 0 && hb + 3 < n) ? x[hb + 3] : INF;
    }
    float4 v;
    v.x = (base + 0 < n) ? x[base + 0] : INF;
    v.y = (base + 1 < n) ? x[base + 1] : INF;
    v.z = (base + 2 < n) ? x[base + 2] : INF;
    v.w = (base + 3 < n) ? x[base + 3] : INF;

    float ps1, ps2, ps3, psc;
    {
        float s2 = fminf(vh.z, vh.w);
        float s1 = fminf(vh.y, s2);
        float s0 = fminf(vh.x, s1);
        float B = s0, A = s0;
        #pragma unroll
        for (int d = 1; d < 32; d <<= 1) {
            float Ap = __shfl_xor_sync(0xffffffffu, A, d);
            if (!(lane & d)) B = fminf(B, Ap);
            A = fminf(A, Ap);
        }
        float sc = __shfl_down_sync(0xffffffffu, B, 1);
        if (lane == 31) sc = INF;
        ps1 = fminf(s1, sc); ps2 = fminf(s2, sc);
        ps3 = fminf(vh.w, sc); psc = sc;
    }

    float p1 = fminf(v.y, v.x);
    float p2 = fminf(v.z, p1);
    float p3 = fminf(v.w, p2);
    float s2 = fminf(v.z, v.w);
    float s1 = fminf(v.y, s2);
    float s0 = fminf(v.x, s1);

    float F = s0, B = s0, A = s0;
    #pragma unroll
    for (int d = 1; d < 32; d <<= 1) {
        float Ap = __shfl_xor_sync(0xffffffffu, A, d);
        if (lane & d) F = fminf(F, Ap);
        else          B = fminf(B, Ap);
        A = fminf(A, Ap);
    }
    float pc = __shfl_up_sync(0xffffffffu, F, 1);
    if (lane == 0) pc = INF;

    float e0 = fminf(fminf(v.x, pc), ps1);
    float e1 = fminf(fminf(p1, pc), ps2);
    float e2 = fminf(fminf(p2, pc), ps3);
    float e3 = fminf(fminf(p3, pc), psc);

    if (base + 0 < n) out[base + 0] = e0;
    if (base + 1 < n) out[base + 1] = e1;
    if (base + 2 < n) out[base + 2] = e2;
    if (base + 3 < n) out[base + 3] = e3;
}

extern "C" void kernel_launch(void* const* d_in, const int* in_sizes, int n_in,
                              void* d_out, int out_size)
{
    const float* x = (const float*)d_in[0];
    float* out = (float*)d_out;
    int n = in_sizes[0];

    int npair = n / (2 * WSZ);                 // full segment-pairs (32768)
    if (npair > 0) {
        int q = npair / TW;                    // 6
        int r = npair % TW;                    // 4352
        swmin_main<<<GRID, BLOCK>>>(x, out, q, r);
    }

    int seg_lo = 2 * npair;
    int nseg = (n + WSZ - 1) / WSZ;
    int tail_segs = nseg - seg_lo;             // 0 for N = 8,388,608
    if (tail_segs > 0) {
        int wpb = BLOCK / 32;
        int blocks = (tail_segs + wpb - 1) / wpb;
        swmin_tail<<<blocks, BLOCK>>>(x, out, n, seg_lo);
    }
}